// round 4
// baseline (speedup 1.0000x reference)
#include <cuda_runtime.h>
#include <cstdint>
#include <cstddef>

// Problem dims
constexpr int kB  = 16;    // batch
constexpr int kN  = 512;   // num inputs
constexpr int kU  = 512;   // num units
constexpr int kT  = 1024;  // time = H*H
constexpr int kH  = 32;    // heads
constexpr int kCB = 512;   // C*B
constexpr float kNEG  = -4294967296.0f;  // float32(-2^32+1)
constexpr float kKEEP = 0.9f;
constexpr float kRKEEP = 1.0f / 0.9f;

constexpr int    kNN     = kN * kN;                 // 262144
constexpr size_t kPSZ    = (size_t)kCB * kNN;       // 134217728
constexpr int    kOUTSZ  = kH * kN * kB * kH;       // 8388608
constexpr int    kATTSZ  = kCB * kN;                // 262144

// Scratch (__device__ globals per allocation-free contract)
__device__ float g_Wt[3 * kU * kN];  // [mat][u][n] transposed weights
__device__ float g_Q[(size_t)kCB * kN * kH];
__device__ float g_K[(size_t)kCB * kN * kH];
__device__ float g_V[(size_t)kCB * kN * kH];
__device__ float g_P[kPSZ];          // raw (masked) scores
__device__ float g_mx[kNN];
__device__ float g_sminv[kNN];       // 1 / (0.9 * sum_exp)

// ---------------- threefry2x32 (exact JAX PRNG, partitionable layout) --------------
__device__ __forceinline__ void tf_round(uint32_t& a, uint32_t& b, int r) {
    a += b;
    b = __funnelshift_l(b, b, r);
    b ^= a;
}
__device__ __forceinline__ void threefry(uint32_t k0, uint32_t k1,
                                         uint32_t& x0, uint32_t& x1) {
    uint32_t k2 = k0 ^ k1 ^ 0x1BD11BDAu;
    x0 += k0; x1 += k1;
    tf_round(x0,x1,13); tf_round(x0,x1,15); tf_round(x0,x1,26); tf_round(x0,x1,6);
    x0 += k1; x1 += k2 + 1u;
    tf_round(x0,x1,17); tf_round(x0,x1,29); tf_round(x0,x1,16); tf_round(x0,x1,24);
    x0 += k2; x1 += k0 + 2u;
    tf_round(x0,x1,13); tf_round(x0,x1,15); tf_round(x0,x1,26); tf_round(x0,x1,6);
    x0 += k0; x1 += k1 + 3u;
    tf_round(x0,x1,17); tf_round(x0,x1,29); tf_round(x0,x1,16); tf_round(x0,x1,24);
    x0 += k1; x1 += k2 + 4u;
    tf_round(x0,x1,13); tf_round(x0,x1,15); tf_round(x0,x1,26); tf_round(x0,x1,6);
    x0 += k2; x1 += k0 + 5u;
}
__device__ __forceinline__ uint32_t rng_bits(uint32_t k1, uint32_t idx) {
    uint32_t x0 = 0u, x1 = idx;
    threefry(0u, k1, x0, x1);
    return x0 ^ x1;
}
__device__ __forceinline__ bool keep_bit(uint32_t bits) {
    float u = __uint_as_float((bits >> 9) | 0x3f800000u) - 1.0f;
    return u < kKEEP;
}

// ---------------- K0: transpose W -> g_Wt[mat][u][n] (runs once, ~3 MB) -----------
__global__ void __launch_bounds__(256) wt_kernel(const float* __restrict__ Qp,
                                                 const float* __restrict__ Kp,
                                                 const float* __restrict__ Vp) {
    __shared__ float t[32][33];
    int mat = blockIdx.z;
    const float* W = (mat == 0) ? Qp : ((mat == 1) ? Kp : Vp);
    int n0 = blockIdx.x * 32, u0 = blockIdx.y * 32;
    int lx = threadIdx.x & 31, ly = threadIdx.x >> 5;   // 8 rows
#pragma unroll
    for (int i = 0; i < 32; i += 8)
        t[ly + i][lx] = W[(size_t)(n0 + ly + i) * kU + u0 + lx];
    __syncthreads();
    float* O = g_Wt + (size_t)mat * kU * kN;
#pragma unroll
    for (int i = 0; i < 32; i += 8)
        O[(size_t)(u0 + ly + i) * kN + n0 + lx] = t[lx][ly + i];
}

// ---------------- K1: projections, 128x128 tile, 8x8 blocking, head layout -------
__global__ void __launch_bounds__(256) proj_kernel(const float* __restrict__ x) {
    int z = blockIdx.z;                 // mat*16 + b
    int mat = z >> 4, b = z & 15;
    const float* Wt = g_Wt + (size_t)mat * kU * kN;
    float* Out      = (mat == 0) ? g_Q : ((mat == 1) ? g_K : g_V);
    const float* X  = x + (size_t)b * kU * kT;

    int n0 = blockIdx.y * 128;
    int t0 = blockIdx.x * 128;

    __shared__ float As[16][128];       // [k][n]
    __shared__ float Bs[16][128];       // [k][t]

    int tid = threadIdx.x;              // 256
    int tx = tid & 15;                  // t group (8 cols)
    int ty = tid >> 4;                  // n group (8 rows)
    int lk = tid >> 5, lc = tid & 31;   // loader: k row, float4 col (2 per thread)

    float acc[8][8] = {};

    float4 a_st[2], b_st[2];
#pragma unroll
    for (int i = 0; i < 2; i++) {
        a_st[i] = *(const float4*)&Wt[(size_t)(lk + i * 8) * kN + n0 + lc * 4];
        b_st[i] = *(const float4*)&X [(size_t)(lk + i * 8) * kT + t0 + lc * 4];
    }

    for (int k0 = 0; k0 < kU; k0 += 16) {
        __syncthreads();
#pragma unroll
        for (int i = 0; i < 2; i++) {
            *(float4*)&As[lk + i * 8][lc * 4] = a_st[i];
            *(float4*)&Bs[lk + i * 8][lc * 4] = b_st[i];
        }
        __syncthreads();
        if (k0 + 16 < kU) {
#pragma unroll
            for (int i = 0; i < 2; i++) {
                a_st[i] = *(const float4*)&Wt[(size_t)(k0 + 16 + lk + i * 8) * kN + n0 + lc * 4];
                b_st[i] = *(const float4*)&X [(size_t)(k0 + 16 + lk + i * 8) * kT + t0 + lc * 4];
            }
        }
#pragma unroll
        for (int k = 0; k < 16; k++) {
            float4 a0 = *(const float4*)&As[k][ty * 8];
            float4 a1 = *(const float4*)&As[k][ty * 8 + 4];
            float4 b0 = *(const float4*)&Bs[k][tx * 8];
            float4 b1 = *(const float4*)&Bs[k][tx * 8 + 4];
            float a[8] = {a0.x,a0.y,a0.z,a0.w,a1.x,a1.y,a1.z,a1.w};
            float bb[8] = {b0.x,b0.y,b0.z,b0.w,b1.x,b1.y,b1.z,b1.w};
#pragma unroll
            for (int i = 0; i < 8; i++)
#pragma unroll
                for (int j = 0; j < 8; j++) acc[i][j] += a[i] * bb[j];
        }
    }

    // write head layout: t -> (c, h); 8 consecutive t stay in one c (tx*8 aligned)
    int tbase = t0 + tx * 8;
    int c = tbase >> 5;
    int h0 = tbase & 31;
#pragma unroll
    for (int i = 0; i < 8; i++) {
        int n = n0 + ty * 8 + i;
        float* dst = &Out[((size_t)(c * 16 + b) * kN + n) * kH + h0];
        *(float4*)dst       = make_float4(acc[i][0], acc[i][1], acc[i][2], acc[i][3]);
        *(float4*)(dst + 4) = make_float4(acc[i][4], acc[i][5], acc[i][6], acc[i][7]);
    }
}

// ---------------- K2: scores[cb,n,m] = Qh.Kh^T with key mask ----------------
__global__ void __launch_bounds__(256) scores_kernel(const int* __restrict__ pm) {
    int cb = blockIdx.z;
    int bb = cb & 15;
    int m0 = blockIdx.x * 64, n0 = blockIdx.y * 64;
    const float* Q = g_Q + (size_t)cb * kN * kH;
    const float* K = g_K + (size_t)cb * kN * kH;

    __shared__ float Qs[64][33];
    __shared__ float Ks[64][33];

    int tid = threadIdx.x;              // 256
#pragma unroll
    for (int i = 0; i < 8; i++) {
        int l = tid + i * 256;
        int r = l >> 5, h = l & 31;
        Qs[r][h] = Q[(size_t)(n0 + r) * kH + h];
        Ks[r][h] = K[(size_t)(m0 + r) * kH + h];
    }
    __syncthreads();

    int tx = tid & 15, ty = tid >> 4;
    float acc[4][4] = {};

#pragma unroll
    for (int h = 0; h < 32; h++) {
        float a[4], bq[4];
#pragma unroll
        for (int i = 0; i < 4; i++) a[i]  = Qs[ty * 4 + i][h];
#pragma unroll
        for (int j = 0; j < 4; j++) bq[j] = Ks[tx * 4 + j][h];
#pragma unroll
        for (int i = 0; i < 4; i++)
#pragma unroll
            for (int j = 0; j < 4; j++) acc[i][j] += a[i] * bq[j];
    }

#pragma unroll
    for (int i = 0; i < 4; i++) {
        int n = n0 + ty * 4 + i;
#pragma unroll
        for (int j = 0; j < 4; j++) {
            int m = m0 + tx * 4 + j;
            float v = (pm[bb * kN + m] == 0) ? kNEG : acc[i][j];
            g_P[((size_t)cb * kN + n) * kN + m] = v;
        }
    }
}

// ---------------- K3: online max & sumexp over axis 0 (cb); store 1/(0.9*sum) -----
__global__ void __launch_bounds__(256) maxsum_kernel() {
    int idx = blockIdx.x * blockDim.x + threadIdx.x;  // 0..N*N-1
    const float* p = g_P + idx;
    float mx = __int_as_float(0xff800000);            // -inf
    float s = 0.0f;
    for (int cb = 0; cb < kCB; cb += 8) {
        float v[8];
#pragma unroll
        for (int u = 0; u < 8; u++) v[u] = p[(size_t)(cb + u) * kNN];
#pragma unroll
        for (int u = 0; u < 8; u++) {
            float vv = v[u];
            if (vv > mx) { s = s * __expf(mx - vv) + 1.0f; mx = vv; }
            else         { s += __expf(vv - mx); }
        }
    }
    g_mx[idx] = mx;
    g_sminv[idx] = 1.0f / (kKEEP * s);
}

// ---------------- K4: ctx = dropout(softmax) @ Vh, warp-per-m-column masked skip --
__global__ void __launch_bounds__(256) ctx_kernel(const int* __restrict__ pm,
                                                  float* __restrict__ out) {
    int cb = blockIdx.y;
    int n0 = blockIdx.x * 64;
    int bb = cb & 15;
    const float* Praw = g_P + (size_t)cb * kNN;
    const float* V = g_V + (size_t)cb * kN * kH;

    __shared__ float Pst[64][66];               // [m][n], even-padded (float2 reads)
    __shared__ __align__(16) float Vs[64][32];  // [m][h]
    __shared__ int pms[kN];

    int tid = threadIdx.x;                      // 256
    for (int i = tid; i < kN; i += 256) pms[i] = pm[bb * kN + i];

    int w = tid >> 5, l = tid & 31;             // warp, lane
    int tx = tid & 7, ty = tid >> 3;            // GEMM mapping
    float acc[2][4] = {};

    __syncthreads();

    for (int m0 = 0; m0 < kN; m0 += 64) {
        // V tile: 64 m x 32 h (512 float4)
#pragma unroll
        for (int i = 0; i < 2; i++) {
            int idx = tid + i * 256;
            int k = idx >> 3, h4 = idx & 7;
            *(float4*)&Vs[k][h4 * 4] =
                *(const float4*)&V[(size_t)(m0 + k) * kH + h4 * 4];
        }
        // P tile: warp owns 8 m-columns, lanes sweep 64 n rows
#pragma unroll 2
        for (int j = 0; j < 8; j++) {
            int ml = w * 8 + j;
            int m = m0 + ml;
            // masked column is exactly zero unless the WHOLE cb-column is masked
            // (then mx == NEG and softmax is uniform) — warp-uniform branch
            if (pms[m] == 0 && g_mx[n0 * kN + m] != kNEG) {
                Pst[ml][l] = 0.0f;
                Pst[ml][l + 32] = 0.0f;
            } else {
#pragma unroll
                for (int rr = 0; rr < 2; rr++) {
                    int n = n0 + l + rr * 32;
                    int nm = n * kN + m;
                    uint32_t gi = (uint32_t)(((size_t)cb * kN + n) * kN + m);
                    float v = Praw[(size_t)n * kN + m];
                    float pr = __expf(v - g_mx[nm]) * g_sminv[nm];
                    uint32_t bits = rng_bits(1u, gi);   // key(1)
                    Pst[ml][l + rr * 32] = keep_bit(bits) ? pr : 0.0f;
                }
            }
        }
        __syncthreads();
#pragma unroll
        for (int k = 0; k < 64; k++) {
            float4 v4 = *(const float4*)&Vs[k][tx * 4];
            float2 p2 = *(const float2*)&Pst[k][ty * 2];
            acc[0][0] += p2.x * v4.x; acc[0][1] += p2.x * v4.y;
            acc[0][2] += p2.x * v4.z; acc[0][3] += p2.x * v4.w;
            acc[1][0] += p2.y * v4.x; acc[1][1] += p2.y * v4.y;
            acc[1][2] += p2.y * v4.z; acc[1][3] += p2.y * v4.w;
        }
        __syncthreads();
    }

    // out[j, n, i*32+h] with cb = i*32+j
    int jpart = (cb & 31) * (kN * kB * kH) + (cb >> 5) * kH;
#pragma unroll
    for (int i = 0; i < 2; i++) {
        int n = n0 + ty * 2 + i;
#pragma unroll
        for (int j = 0; j < 4; j++) {
            int h = tx * 4 + j;
            int oidx = jpart + n * (kB * kH) + h;
            uint32_t bits = rng_bits(2u, (uint32_t)oidx);  // key(2)
            out[oidx] = keep_bit(bits) ? acc[i][j] * kRKEEP : 0.0f;
        }
    }
}

// ---------------- K5: attention = dropout(probs)[:, N-1, :] recomputed ------------
__global__ void __launch_bounds__(256) attn_kernel(float* __restrict__ out) {
    int idx = blockIdx.x * blockDim.x + threadIdx.x;  // 0..kATTSZ-1
    int cb = idx >> 9, m = idx & 511;
    uint32_t gi = (uint32_t)(((size_t)cb * kN + (kN - 1)) * kN + m);
    int nm = (kN - 1) * kN + m;
    float v = g_P[gi];
    float pr = __expf(v - g_mx[nm]) * g_sminv[nm];
    uint32_t bits = rng_bits(1u, gi);
    out[kOUTSZ + idx] = keep_bit(bits) ? pr : 0.0f;
}

extern "C" void kernel_launch(void* const* d_in, const int* in_sizes, int n_in,
                              void* d_out, int out_size) {
    const float* x  = (const float*)d_in[0];
    const float* Qp = (const float*)d_in[1];
    const float* Kp = (const float*)d_in[2];
    const float* Vp = (const float*)d_in[3];
    const int*   pm = (const int*)d_in[4];
    float* out = (float*)d_out;

    wt_kernel    <<<dim3(16, 16, 3), 256>>>(Qp, Kp, Vp);
    proj_kernel  <<<dim3(kT / 128, kN / 128, 48), 256>>>(x);
    scores_kernel<<<dim3(kN / 64, kN / 64, kCB), 256>>>(pm);
    maxsum_kernel<<<kNN / 256, 256>>>();
    ctx_kernel   <<<dim3(kN / 64, kCB), 256>>>(pm, out);
    if (out_size >= kOUTSZ + kATTSZ) {
        attn_kernel<<<kATTSZ / 256, 256>>>(out);
    }
}

// round 5
// speedup vs baseline: 1.0610x; 1.0610x over previous
#include <cuda_runtime.h>
#include <cstdint>
#include <cstddef>

// Problem dims
constexpr int kB  = 16;    // batch
constexpr int kN  = 512;   // num inputs
constexpr int kU  = 512;   // num units
constexpr int kT  = 1024;  // time = H*H
constexpr int kH  = 32;    // heads
constexpr int kCB = 512;   // C*B
constexpr float kNEG  = -4294967296.0f;  // float32(-2^32+1)
constexpr float kKEEP = 0.9f;
constexpr float kRKEEP = 1.0f / 0.9f;

constexpr int    kNN     = kN * kN;                 // 262144
constexpr size_t kPSZ    = (size_t)kCB * kNN;       // 134217728
constexpr int    kOUTSZ  = kH * kN * kB * kH;       // 8388608
constexpr int    kATTSZ  = kCB * kN;                // 262144

// Scratch (__device__ globals per allocation-free contract)
__device__ float g_Q[(size_t)kCB * kN * kH];
__device__ float g_K[(size_t)kCB * kN * kH];
__device__ float g_V[(size_t)kCB * kN * kH];
__device__ float g_P[kPSZ];          // raw (masked) scores
__device__ float g_mx[kNN];
__device__ float g_sminv[kNN];       // 1 / (0.9 * sum_exp)

// ---------------- threefry2x32 (exact JAX PRNG, partitionable layout) --------------
__device__ __forceinline__ void tf_round(uint32_t& a, uint32_t& b, int r) {
    a += b;
    b = __funnelshift_l(b, b, r);
    b ^= a;
}
__device__ __forceinline__ void threefry(uint32_t k0, uint32_t k1,
                                         uint32_t& x0, uint32_t& x1) {
    uint32_t k2 = k0 ^ k1 ^ 0x1BD11BDAu;
    x0 += k0; x1 += k1;
    tf_round(x0,x1,13); tf_round(x0,x1,15); tf_round(x0,x1,26); tf_round(x0,x1,6);
    x0 += k1; x1 += k2 + 1u;
    tf_round(x0,x1,17); tf_round(x0,x1,29); tf_round(x0,x1,16); tf_round(x0,x1,24);
    x0 += k2; x1 += k0 + 2u;
    tf_round(x0,x1,13); tf_round(x0,x1,15); tf_round(x0,x1,26); tf_round(x0,x1,6);
    x0 += k0; x1 += k1 + 3u;
    tf_round(x0,x1,17); tf_round(x0,x1,29); tf_round(x0,x1,16); tf_round(x0,x1,24);
    x0 += k1; x1 += k2 + 4u;
    tf_round(x0,x1,13); tf_round(x0,x1,15); tf_round(x0,x1,26); tf_round(x0,x1,6);
    x0 += k2; x1 += k0 + 5u;
}
__device__ __forceinline__ uint32_t rng_bits(uint32_t k1, uint32_t idx) {
    uint32_t x0 = 0u, x1 = idx;
    threefry(0u, k1, x0, x1);
    return x0 ^ x1;
}
__device__ __forceinline__ bool keep_bit(uint32_t bits) {
    float u = __uint_as_float((bits >> 9) | 0x3f800000u) - 1.0f;
    return u < kKEEP;
}

// ---------------- tf32 helpers ----------------
__device__ __forceinline__ uint32_t f2tf32(float v) {
    uint32_t r;
    asm("cvt.rna.tf32.f32 %0, %1;" : "=r"(r) : "f"(v));
    return r;
}
__device__ __forceinline__ void split_tf32(float v, float& hi, float& lo) {
    uint32_t h = f2tf32(v);
    hi = __uint_as_float(h);
    lo = v - hi;     // exact; then implicitly rounded again at mma operand cvt below
}
__device__ __forceinline__ void mma_tf32(float& d0, float& d1, float& d2, float& d3,
                                         uint32_t a0, uint32_t a1, uint32_t a2, uint32_t a3,
                                         uint32_t b0, uint32_t b1) {
    asm volatile(
        "mma.sync.aligned.m16n8k8.row.col.f32.tf32.tf32.f32 "
        "{%0,%1,%2,%3}, {%4,%5,%6,%7}, {%8,%9}, {%0,%1,%2,%3};"
        : "+f"(d0), "+f"(d1), "+f"(d2), "+f"(d3)
        : "r"(a0), "r"(a1), "r"(a2), "r"(a3), "r"(b0), "r"(b1));
}

// ---------------- K1: projections via tf32 mma (2-term split, 3 MMAs) -------------
// Out[cb=c*16+b][n][h] = sum_u W[n][u] * x[b][u][t],  t = c*32+h
// A = W (row-major [m=n][k=u]),  B = x (col-major frag from [k=u][n=t])
__global__ void __launch_bounds__(256) proj_kernel(const float* __restrict__ x,
                                                   const float* __restrict__ Qp,
                                                   const float* __restrict__ Kp,
                                                   const float* __restrict__ Vp) {
    int z = blockIdx.z;                 // mat*16 + b
    int mat = z >> 4, b = z & 15;
    const float* W  = (mat == 0) ? Qp : ((mat == 1) ? Kp : Vp);
    float* Out      = (mat == 0) ? g_Q : ((mat == 1) ? g_K : g_V);
    const float* X  = x + (size_t)b * kU * kT;

    int n0 = blockIdx.y * 128;          // output n (m-dim)
    int t0 = blockIdx.x * 128;          // output t (n-dim)

    __shared__ float Wh[128][20];       // [n][k] hi plane (stride 20: conflict-free frags)
    __shared__ float Wl[128][20];       // lo plane
    __shared__ float Xh[16][136];       // [k][t] hi plane (stride 136)
    __shared__ float Xl[16][136];       // lo plane

    int tid = threadIdx.x;              // 256
    int w   = tid >> 5;                 // warp 0..7
    int lane= tid & 31;
    int g   = lane >> 2;                // group 0..7
    int tig = lane & 3;                 // thread-in-group

    int wm = (w & 3) * 32;              // warp m-offset within 128
    int wn = (w >> 2) * 64;             // warp t-offset within 128

    float acc[2][8][4] = {};            // [m-tile][n-tile][frag]

    for (int k0 = 0; k0 < kU; k0 += 16) {
        __syncthreads();
        // fill W tile: 128 n x 16 k  (512 float4, 2 per thread)
#pragma unroll
        for (int i = 0; i < 2; i++) {
            int idx = tid + i * 256;
            int n = idx >> 2, c4 = idx & 3;
            float4 v = *(const float4*)&W[(size_t)(n0 + n) * kU + k0 + c4 * 4];
            float h0,l0,h1,l1,h2,l2,h3,l3;
            split_tf32(v.x, h0, l0); split_tf32(v.y, h1, l1);
            split_tf32(v.z, h2, l2); split_tf32(v.w, h3, l3);
            Wh[n][c4*4+0] = h0; Wh[n][c4*4+1] = h1; Wh[n][c4*4+2] = h2; Wh[n][c4*4+3] = h3;
            Wl[n][c4*4+0] = l0; Wl[n][c4*4+1] = l1; Wl[n][c4*4+2] = l2; Wl[n][c4*4+3] = l3;
        }
        // fill X tile: 16 k x 128 t
#pragma unroll
        for (int i = 0; i < 2; i++) {
            int idx = tid + i * 256;
            int k = idx >> 5, c4 = idx & 31;
            float4 v = *(const float4*)&X[(size_t)(k0 + k) * kT + t0 + c4 * 4];
            float h0,l0,h1,l1,h2,l2,h3,l3;
            split_tf32(v.x, h0, l0); split_tf32(v.y, h1, l1);
            split_tf32(v.z, h2, l2); split_tf32(v.w, h3, l3);
            Xh[k][c4*4+0] = h0; Xh[k][c4*4+1] = h1; Xh[k][c4*4+2] = h2; Xh[k][c4*4+3] = h3;
            Xl[k][c4*4+0] = l0; Xl[k][c4*4+1] = l1; Xl[k][c4*4+2] = l2; Xl[k][c4*4+3] = l3;
        }
        __syncthreads();

#pragma unroll
        for (int kk = 0; kk < 16; kk += 8) {
            // A fragments (2 m-tiles), hi and lo
            uint32_t ah[2][4], al[2][4];
#pragma unroll
            for (int mt = 0; mt < 2; mt++) {
                int r = wm + mt * 16 + g;
                ah[mt][0] = __float_as_uint(Wh[r    ][kk + tig    ]);
                ah[mt][1] = __float_as_uint(Wh[r + 8][kk + tig    ]);
                ah[mt][2] = __float_as_uint(Wh[r    ][kk + tig + 4]);
                ah[mt][3] = __float_as_uint(Wh[r + 8][kk + tig + 4]);
                al[mt][0] = f2tf32(Wl[r    ][kk + tig    ]);
                al[mt][1] = f2tf32(Wl[r + 8][kk + tig    ]);
                al[mt][2] = f2tf32(Wl[r    ][kk + tig + 4]);
                al[mt][3] = f2tf32(Wl[r + 8][kk + tig + 4]);
            }
#pragma unroll
            for (int j = 0; j < 8; j++) {
                int col = wn + j * 8 + g;
                uint32_t bh0 = __float_as_uint(Xh[kk + tig    ][col]);
                uint32_t bh1 = __float_as_uint(Xh[kk + tig + 4][col]);
                uint32_t bl0 = f2tf32(Xl[kk + tig    ][col]);
                uint32_t bl1 = f2tf32(Xl[kk + tig + 4][col]);
#pragma unroll
                for (int mt = 0; mt < 2; mt++) {
                    mma_tf32(acc[mt][j][0], acc[mt][j][1], acc[mt][j][2], acc[mt][j][3],
                             ah[mt][0], ah[mt][1], ah[mt][2], ah[mt][3], bh0, bh1);
                    mma_tf32(acc[mt][j][0], acc[mt][j][1], acc[mt][j][2], acc[mt][j][3],
                             ah[mt][0], ah[mt][1], ah[mt][2], ah[mt][3], bl0, bl1);
                    mma_tf32(acc[mt][j][0], acc[mt][j][1], acc[mt][j][2], acc[mt][j][3],
                             al[mt][0], al[mt][1], al[mt][2], al[mt][3], bh0, bh1);
                }
            }
        }
    }

    // epilogue: head layout Out[(c*16+b)*N + n]*32 + h,  t = c*32+h
#pragma unroll
    for (int mt = 0; mt < 2; mt++) {
        int r0 = n0 + wm + mt * 16 + g;
#pragma unroll
        for (int j = 0; j < 8; j++) {
            int t = t0 + wn + j * 8 + 2 * tig;
            int c = t >> 5, h = t & 31;
            float* base = &Out[((size_t)(c * 16 + b) * kN) * kH + h];
            *(float2*)&base[(size_t)r0 * kH]       = make_float2(acc[mt][j][0], acc[mt][j][1]);
            *(float2*)&base[(size_t)(r0 + 8) * kH] = make_float2(acc[mt][j][2], acc[mt][j][3]);
        }
    }
}

// ---------------- K2: scores[cb,n,m] = Qh.Kh^T with key mask ----------------
__global__ void __launch_bounds__(256) scores_kernel(const int* __restrict__ pm) {
    int cb = blockIdx.z;
    int bb = cb & 15;
    int m0 = blockIdx.x * 64, n0 = blockIdx.y * 64;
    const float* Q = g_Q + (size_t)cb * kN * kH;
    const float* K = g_K + (size_t)cb * kN * kH;

    __shared__ float Qs[64][33];
    __shared__ float Ks[64][33];

    int tid = threadIdx.x;              // 256
#pragma unroll
    for (int i = 0; i < 8; i++) {
        int l = tid + i * 256;
        int r = l >> 5, h = l & 31;
        Qs[r][h] = Q[(size_t)(n0 + r) * kH + h];
        Ks[r][h] = K[(size_t)(m0 + r) * kH + h];
    }
    __syncthreads();

    int tx = tid & 15, ty = tid >> 4;
    float acc[4][4] = {};

#pragma unroll
    for (int h = 0; h < 32; h++) {
        float a[4], bq[4];
#pragma unroll
        for (int i = 0; i < 4; i++) a[i]  = Qs[ty * 4 + i][h];
#pragma unroll
        for (int j = 0; j < 4; j++) bq[j] = Ks[tx * 4 + j][h];
#pragma unroll
        for (int i = 0; i < 4; i++)
#pragma unroll
            for (int j = 0; j < 4; j++) acc[i][j] += a[i] * bq[j];
    }

#pragma unroll
    for (int i = 0; i < 4; i++) {
        int n = n0 + ty * 4 + i;
#pragma unroll
        for (int j = 0; j < 4; j++) {
            int m = m0 + tx * 4 + j;
            float v = (pm[bb * kN + m] == 0) ? kNEG : acc[i][j];
            g_P[((size_t)cb * kN + n) * kN + m] = v;
        }
    }
}

// ---------------- K3: online max & sumexp over axis 0 (cb); store 1/(0.9*sum) -----
__global__ void __launch_bounds__(256) maxsum_kernel() {
    int idx = blockIdx.x * blockDim.x + threadIdx.x;  // 0..N*N-1
    const float* p = g_P + idx;
    float mx = __int_as_float(0xff800000);            // -inf
    float s = 0.0f;
    for (int cb = 0; cb < kCB; cb += 8) {
        float v[8];
#pragma unroll
        for (int u = 0; u < 8; u++) v[u] = p[(size_t)(cb + u) * kNN];
#pragma unroll
        for (int u = 0; u < 8; u++) {
            float vv = v[u];
            if (vv > mx) { s = s * __expf(mx - vv) + 1.0f; mx = vv; }
            else         { s += __expf(vv - mx); }
        }
    }
    g_mx[idx] = mx;
    g_sminv[idx] = 1.0f / (kKEEP * s);
}

// ---------------- K4: ctx = dropout(softmax) @ Vh, warp-per-m-column masked skip --
__global__ void __launch_bounds__(256) ctx_kernel(const int* __restrict__ pm,
                                                  float* __restrict__ out) {
    int cb = blockIdx.y;
    int n0 = blockIdx.x * 64;
    int bb = cb & 15;
    const float* Praw = g_P + (size_t)cb * kNN;
    const float* V = g_V + (size_t)cb * kN * kH;

    __shared__ float Pst[64][66];               // [m][n], even-padded (float2 reads)
    __shared__ __align__(16) float Vs[64][32];  // [m][h]
    __shared__ int pms[kN];

    int tid = threadIdx.x;                      // 256
    for (int i = tid; i < kN; i += 256) pms[i] = pm[bb * kN + i];

    int w = tid >> 5, l = tid & 31;             // warp, lane
    int tx = tid & 7, ty = tid >> 3;            // GEMM mapping
    float acc[2][4] = {};

    __syncthreads();

    for (int m0 = 0; m0 < kN; m0 += 64) {
        // V tile: 64 m x 32 h (512 float4)
#pragma unroll
        for (int i = 0; i < 2; i++) {
            int idx = tid + i * 256;
            int k = idx >> 3, h4 = idx & 7;
            *(float4*)&Vs[k][h4 * 4] =
                *(const float4*)&V[(size_t)(m0 + k) * kH + h4 * 4];
        }
        // P tile: warp owns 8 m-columns, lanes sweep 64 n rows
#pragma unroll 2
        for (int j = 0; j < 8; j++) {
            int ml = w * 8 + j;
            int m = m0 + ml;
            if (pms[m] == 0 && g_mx[n0 * kN + m] != kNEG) {
                Pst[ml][l] = 0.0f;
                Pst[ml][l + 32] = 0.0f;
            } else {
#pragma unroll
                for (int rr = 0; rr < 2; rr++) {
                    int n = n0 + l + rr * 32;
                    int nm = n * kN + m;
                    uint32_t gi = (uint32_t)(((size_t)cb * kN + n) * kN + m);
                    float v = Praw[(size_t)n * kN + m];
                    float pr = __expf(v - g_mx[nm]) * g_sminv[nm];
                    uint32_t bits = rng_bits(1u, gi);   // key(1)
                    Pst[ml][l + rr * 32] = keep_bit(bits) ? pr : 0.0f;
                }
            }
        }
        __syncthreads();
#pragma unroll
        for (int k = 0; k < 64; k++) {
            float4 v4 = *(const float4*)&Vs[k][tx * 4];
            float2 p2 = *(const float2*)&Pst[k][ty * 2];
            acc[0][0] += p2.x * v4.x; acc[0][1] += p2.x * v4.y;
            acc[0][2] += p2.x * v4.z; acc[0][3] += p2.x * v4.w;
            acc[1][0] += p2.y * v4.x; acc[1][1] += p2.y * v4.y;
            acc[1][2] += p2.y * v4.z; acc[1][3] += p2.y * v4.w;
        }
        __syncthreads();
    }

    // out[j, n, i*32+h] with cb = i*32+j
    int jpart = (cb & 31) * (kN * kB * kH) + (cb >> 5) * kH;
#pragma unroll
    for (int i = 0; i < 2; i++) {
        int n = n0 + ty * 2 + i;
#pragma unroll
        for (int j = 0; j < 4; j++) {
            int h = tx * 4 + j;
            int oidx = jpart + n * (kB * kH) + h;
            uint32_t bits = rng_bits(2u, (uint32_t)oidx);  // key(2)
            out[oidx] = keep_bit(bits) ? acc[i][j] * kRKEEP : 0.0f;
        }
    }
}

// ---------------- K5: attention = dropout(probs)[:, N-1, :] recomputed ------------
__global__ void __launch_bounds__(256) attn_kernel(float* __restrict__ out) {
    int idx = blockIdx.x * blockDim.x + threadIdx.x;  // 0..kATTSZ-1
    int cb = idx >> 9, m = idx & 511;
    uint32_t gi = (uint32_t)(((size_t)cb * kN + (kN - 1)) * kN + m);
    int nm = (kN - 1) * kN + m;
    float v = g_P[gi];
    float pr = __expf(v - g_mx[nm]) * g_sminv[nm];
    uint32_t bits = rng_bits(1u, gi);
    out[kOUTSZ + idx] = keep_bit(bits) ? pr : 0.0f;
}

extern "C" void kernel_launch(void* const* d_in, const int* in_sizes, int n_in,
                              void* d_out, int out_size) {
    const float* x  = (const float*)d_in[0];
    const float* Qp = (const float*)d_in[1];
    const float* Kp = (const float*)d_in[2];
    const float* Vp = (const float*)d_in[3];
    const int*   pm = (const int*)d_in[4];
    float* out = (float*)d_out;

    proj_kernel  <<<dim3(kT / 128, kN / 128, 48), 256>>>(x, Qp, Kp, Vp);
    scores_kernel<<<dim3(kN / 64, kN / 64, kCB), 256>>>(pm);
    maxsum_kernel<<<kNN / 256, 256>>>();
    ctx_kernel   <<<dim3(kN / 64, kCB), 256>>>(pm, out);
    if (out_size >= kOUTSZ + kATTSZ) {
        attn_kernel<<<kATTSZ / 256, 256>>>(out);
    }
}

// round 6
// speedup vs baseline: 1.1334x; 1.0682x over previous
#include <cuda_runtime.h>
#include <cstdint>
#include <cstddef>

// Problem dims
constexpr int kB  = 16;    // batch
constexpr int kN  = 512;   // num inputs
constexpr int kU  = 512;   // num units
constexpr int kT  = 1024;  // time = H*H
constexpr int kH  = 32;    // heads
constexpr int kCB = 512;   // C*B
constexpr float kNEG  = -4294967296.0f;  // float32(-2^32+1)
constexpr float kKEEP = 0.9f;
constexpr float kRKEEP = 1.0f / 0.9f;

constexpr int    kNN     = kN * kN;                 // 262144
constexpr size_t kPSZ    = (size_t)kCB * kNN;       // 134217728
constexpr int    kOUTSZ  = kH * kN * kB * kH;       // 8388608
constexpr int    kATTSZ  = kCB * kN;                // 262144

// Scratch (__device__ globals per allocation-free contract)
__device__ float g_Q[(size_t)kCB * kN * kH];
__device__ float g_K[(size_t)kCB * kN * kH];
__device__ float g_V[(size_t)kCB * kN * kH];
__device__ float g_P[kPSZ];          // raw (masked) scores
__device__ float g_mx[kNN];
__device__ float g_sminv[kNN];       // 1 / (0.9 * sum_exp)

// ---------------- threefry2x32 (exact JAX PRNG, partitionable layout) --------------
__device__ __forceinline__ void tf_round(uint32_t& a, uint32_t& b, int r) {
    a += b;
    b = __funnelshift_l(b, b, r);
    b ^= a;
}
__device__ __forceinline__ void threefry(uint32_t k0, uint32_t k1,
                                         uint32_t& x0, uint32_t& x1) {
    uint32_t k2 = k0 ^ k1 ^ 0x1BD11BDAu;
    x0 += k0; x1 += k1;
    tf_round(x0,x1,13); tf_round(x0,x1,15); tf_round(x0,x1,26); tf_round(x0,x1,6);
    x0 += k1; x1 += k2 + 1u;
    tf_round(x0,x1,17); tf_round(x0,x1,29); tf_round(x0,x1,16); tf_round(x0,x1,24);
    x0 += k2; x1 += k0 + 2u;
    tf_round(x0,x1,13); tf_round(x0,x1,15); tf_round(x0,x1,26); tf_round(x0,x1,6);
    x0 += k0; x1 += k1 + 3u;
    tf_round(x0,x1,17); tf_round(x0,x1,29); tf_round(x0,x1,16); tf_round(x0,x1,24);
    x0 += k1; x1 += k2 + 4u;
    tf_round(x0,x1,13); tf_round(x0,x1,15); tf_round(x0,x1,26); tf_round(x0,x1,6);
    x0 += k2; x1 += k0 + 5u;
}
__device__ __forceinline__ uint32_t rng_bits(uint32_t k1, uint32_t idx) {
    uint32_t x0 = 0u, x1 = idx;
    threefry(0u, k1, x0, x1);
    return x0 ^ x1;
}
__device__ __forceinline__ bool keep_bit(uint32_t bits) {
    float u = __uint_as_float((bits >> 9) | 0x3f800000u) - 1.0f;
    return u < kKEEP;
}

// ---------------- tf32 helpers ----------------
__device__ __forceinline__ uint32_t f2tf32(float v) {
    uint32_t r;
    asm("cvt.rna.tf32.f32 %0, %1;" : "=r"(r) : "f"(v));
    return r;
}
__device__ __forceinline__ void split_tf32(float v, float& hi, float& lo) {
    uint32_t h = f2tf32(v);
    hi = __uint_as_float(h);
    lo = v - hi;
}
__device__ __forceinline__ void mma_tf32(float& d0, float& d1, float& d2, float& d3,
                                         uint32_t a0, uint32_t a1, uint32_t a2, uint32_t a3,
                                         uint32_t b0, uint32_t b1) {
    asm volatile(
        "mma.sync.aligned.m16n8k8.row.col.f32.tf32.tf32.f32 "
        "{%0,%1,%2,%3}, {%4,%5,%6,%7}, {%8,%9}, {%0,%1,%2,%3};"
        : "+f"(d0), "+f"(d1), "+f"(d2), "+f"(d3)
        : "r"(a0), "r"(a1), "r"(a2), "r"(a3), "r"(b0), "r"(b1));
}

// ---------------- K1: projections via tf32 mma (2-term split, 3 MMAs) -------------
__global__ void __launch_bounds__(256) proj_kernel(const float* __restrict__ x,
                                                   const float* __restrict__ Qp,
                                                   const float* __restrict__ Kp,
                                                   const float* __restrict__ Vp) {
    int z = blockIdx.z;                 // mat*16 + b
    int mat = z >> 4, b = z & 15;
    const float* W  = (mat == 0) ? Qp : ((mat == 1) ? Kp : Vp);
    float* Out      = (mat == 0) ? g_Q : ((mat == 1) ? g_K : g_V);
    const float* X  = x + (size_t)b * kU * kT;

    int n0 = blockIdx.y * 128;          // output n (m-dim)
    int t0 = blockIdx.x * 128;          // output t (n-dim)

    __shared__ float Wh[128][20];
    __shared__ float Wl[128][20];
    __shared__ float Xh[16][136];
    __shared__ float Xl[16][136];

    int tid = threadIdx.x;              // 256
    int w   = tid >> 5;
    int lane= tid & 31;
    int g   = lane >> 2;
    int tig = lane & 3;

    int wm = (w & 3) * 32;
    int wn = (w >> 2) * 64;

    float acc[2][8][4] = {};

    for (int k0 = 0; k0 < kU; k0 += 16) {
        __syncthreads();
#pragma unroll
        for (int i = 0; i < 2; i++) {
            int idx = tid + i * 256;
            int n = idx >> 2, c4 = idx & 3;
            float4 v = *(const float4*)&W[(size_t)(n0 + n) * kU + k0 + c4 * 4];
            float h0,l0,h1,l1,h2,l2,h3,l3;
            split_tf32(v.x, h0, l0); split_tf32(v.y, h1, l1);
            split_tf32(v.z, h2, l2); split_tf32(v.w, h3, l3);
            Wh[n][c4*4+0] = h0; Wh[n][c4*4+1] = h1; Wh[n][c4*4+2] = h2; Wh[n][c4*4+3] = h3;
            Wl[n][c4*4+0] = l0; Wl[n][c4*4+1] = l1; Wl[n][c4*4+2] = l2; Wl[n][c4*4+3] = l3;
        }
#pragma unroll
        for (int i = 0; i < 2; i++) {
            int idx = tid + i * 256;
            int k = idx >> 5, c4 = idx & 31;
            float4 v = *(const float4*)&X[(size_t)(k0 + k) * kT + t0 + c4 * 4];
            float h0,l0,h1,l1,h2,l2,h3,l3;
            split_tf32(v.x, h0, l0); split_tf32(v.y, h1, l1);
            split_tf32(v.z, h2, l2); split_tf32(v.w, h3, l3);
            Xh[k][c4*4+0] = h0; Xh[k][c4*4+1] = h1; Xh[k][c4*4+2] = h2; Xh[k][c4*4+3] = h3;
            Xl[k][c4*4+0] = l0; Xl[k][c4*4+1] = l1; Xl[k][c4*4+2] = l2; Xl[k][c4*4+3] = l3;
        }
        __syncthreads();

#pragma unroll
        for (int kk = 0; kk < 16; kk += 8) {
            uint32_t ah[2][4], al[2][4];
#pragma unroll
            for (int mt = 0; mt < 2; mt++) {
                int r = wm + mt * 16 + g;
                ah[mt][0] = __float_as_uint(Wh[r    ][kk + tig    ]);
                ah[mt][1] = __float_as_uint(Wh[r + 8][kk + tig    ]);
                ah[mt][2] = __float_as_uint(Wh[r    ][kk + tig + 4]);
                ah[mt][3] = __float_as_uint(Wh[r + 8][kk + tig + 4]);
                al[mt][0] = f2tf32(Wl[r    ][kk + tig    ]);
                al[mt][1] = f2tf32(Wl[r + 8][kk + tig    ]);
                al[mt][2] = f2tf32(Wl[r    ][kk + tig + 4]);
                al[mt][3] = f2tf32(Wl[r + 8][kk + tig + 4]);
            }
#pragma unroll
            for (int j = 0; j < 8; j++) {
                int col = wn + j * 8 + g;
                uint32_t bh0 = __float_as_uint(Xh[kk + tig    ][col]);
                uint32_t bh1 = __float_as_uint(Xh[kk + tig + 4][col]);
                uint32_t bl0 = f2tf32(Xl[kk + tig    ][col]);
                uint32_t bl1 = f2tf32(Xl[kk + tig + 4][col]);
#pragma unroll
                for (int mt = 0; mt < 2; mt++) {
                    mma_tf32(acc[mt][j][0], acc[mt][j][1], acc[mt][j][2], acc[mt][j][3],
                             ah[mt][0], ah[mt][1], ah[mt][2], ah[mt][3], bh0, bh1);
                    mma_tf32(acc[mt][j][0], acc[mt][j][1], acc[mt][j][2], acc[mt][j][3],
                             ah[mt][0], ah[mt][1], ah[mt][2], ah[mt][3], bl0, bl1);
                    mma_tf32(acc[mt][j][0], acc[mt][j][1], acc[mt][j][2], acc[mt][j][3],
                             al[mt][0], al[mt][1], al[mt][2], al[mt][3], bh0, bh1);
                }
            }
        }
    }

#pragma unroll
    for (int mt = 0; mt < 2; mt++) {
        int r0 = n0 + wm + mt * 16 + g;
#pragma unroll
        for (int j = 0; j < 8; j++) {
            int t = t0 + wn + j * 8 + 2 * tig;
            int c = t >> 5, h = t & 31;
            float* base = &Out[((size_t)(c * 16 + b) * kN) * kH + h];
            *(float2*)&base[(size_t)r0 * kH]       = make_float2(acc[mt][j][0], acc[mt][j][1]);
            *(float2*)&base[(size_t)(r0 + 8) * kH] = make_float2(acc[mt][j][2], acc[mt][j][3]);
        }
    }
}

// ---------------- K2: scores via tf32 mma, K-dim = h = 32, no k-loop --------------
// A = Qh (row-major [n][h]), B = Kh (col-major frag from [m][h]); mask in epilogue.
__global__ void __launch_bounds__(256) scores_kernel(const int* __restrict__ pm) {
    int cb = blockIdx.z;
    int bb = cb & 15;
    int m0 = blockIdx.x * 64, n0 = blockIdx.y * 64;
    const float* Q = g_Q + (size_t)cb * kN * kH;
    const float* K = g_K + (size_t)cb * kN * kH;

    __shared__ float Qh[64][36], Ql[64][36];
    __shared__ float Kh2[64][36], Kl[64][36];
    __shared__ int pmsk[64];

    int tid = threadIdx.x;              // 256
    if (tid < 64) pmsk[tid] = pm[bb * kN + m0 + tid];

    // fill both 64x32 tiles, split hi/lo (2 float4 per tile per thread)
#pragma unroll
    for (int i = 0; i < 2; i++) {
        int idx = tid + i * 256;
        int r = idx >> 3, c4 = idx & 7;
        float4 v = *(const float4*)&Q[(size_t)(n0 + r) * kH + c4 * 4];
        float h0,l0,h1,l1,h2,l2,h3,l3;
        split_tf32(v.x, h0, l0); split_tf32(v.y, h1, l1);
        split_tf32(v.z, h2, l2); split_tf32(v.w, h3, l3);
        Qh[r][c4*4+0]=h0; Qh[r][c4*4+1]=h1; Qh[r][c4*4+2]=h2; Qh[r][c4*4+3]=h3;
        Ql[r][c4*4+0]=l0; Ql[r][c4*4+1]=l1; Ql[r][c4*4+2]=l2; Ql[r][c4*4+3]=l3;
        float4 u = *(const float4*)&K[(size_t)(m0 + r) * kH + c4 * 4];
        split_tf32(u.x, h0, l0); split_tf32(u.y, h1, l1);
        split_tf32(u.z, h2, l2); split_tf32(u.w, h3, l3);
        Kh2[r][c4*4+0]=h0; Kh2[r][c4*4+1]=h1; Kh2[r][c4*4+2]=h2; Kh2[r][c4*4+3]=h3;
        Kl[r][c4*4+0]=l0; Kl[r][c4*4+1]=l1; Kl[r][c4*4+2]=l2; Kl[r][c4*4+3]=l3;
    }
    __syncthreads();

    int w = tid >> 5, lane = tid & 31;
    int g = lane >> 2, tig = lane & 3;
    int wm = (w & 1) * 32;              // n offset within 64
    int wnn = (w >> 1) * 16;            // m offset within 64

    float acc[2][2][4] = {};

#pragma unroll
    for (int kk = 0; kk < 32; kk += 8) {
        uint32_t ah[2][4], al[2][4];
#pragma unroll
        for (int mt = 0; mt < 2; mt++) {
            int r = wm + mt * 16 + g;
            ah[mt][0] = __float_as_uint(Qh[r    ][kk + tig    ]);
            ah[mt][1] = __float_as_uint(Qh[r + 8][kk + tig    ]);
            ah[mt][2] = __float_as_uint(Qh[r    ][kk + tig + 4]);
            ah[mt][3] = __float_as_uint(Qh[r + 8][kk + tig + 4]);
            al[mt][0] = f2tf32(Ql[r    ][kk + tig    ]);
            al[mt][1] = f2tf32(Ql[r + 8][kk + tig    ]);
            al[mt][2] = f2tf32(Ql[r    ][kk + tig + 4]);
            al[mt][3] = f2tf32(Ql[r + 8][kk + tig + 4]);
        }
#pragma unroll
        for (int j = 0; j < 2; j++) {
            int col = wnn + j * 8 + g;
            uint32_t bh0 = __float_as_uint(Kh2[col][kk + tig    ]);
            uint32_t bh1 = __float_as_uint(Kh2[col][kk + tig + 4]);
            uint32_t bl0 = f2tf32(Kl[col][kk + tig    ]);
            uint32_t bl1 = f2tf32(Kl[col][kk + tig + 4]);
#pragma unroll
            for (int mt = 0; mt < 2; mt++) {
                mma_tf32(acc[mt][j][0], acc[mt][j][1], acc[mt][j][2], acc[mt][j][3],
                         ah[mt][0], ah[mt][1], ah[mt][2], ah[mt][3], bh0, bh1);
                mma_tf32(acc[mt][j][0], acc[mt][j][1], acc[mt][j][2], acc[mt][j][3],
                         ah[mt][0], ah[mt][1], ah[mt][2], ah[mt][3], bl0, bl1);
                mma_tf32(acc[mt][j][0], acc[mt][j][1], acc[mt][j][2], acc[mt][j][3],
                         al[mt][0], al[mt][1], al[mt][2], al[mt][3], bh0, bh1);
            }
        }
    }

    // epilogue with key mask (exact NEG)
#pragma unroll
    for (int mt = 0; mt < 2; mt++) {
        int n = n0 + wm + mt * 16 + g;
#pragma unroll
        for (int j = 0; j < 2; j++) {
            int mc = wnn + j * 8 + 2 * tig;
            int m = m0 + mc;
            float c0 = (pmsk[mc]     == 0) ? kNEG : acc[mt][j][0];
            float c1 = (pmsk[mc + 1] == 0) ? kNEG : acc[mt][j][1];
            float c2 = (pmsk[mc]     == 0) ? kNEG : acc[mt][j][2];
            float c3 = (pmsk[mc + 1] == 0) ? kNEG : acc[mt][j][3];
            *(float2*)&g_P[((size_t)cb * kN + n) * kN + m]     = make_float2(c0, c1);
            *(float2*)&g_P[((size_t)cb * kN + n + 8) * kN + m] = make_float2(c2, c3);
        }
    }
}

// ---------------- K3: online max & sumexp over axis 0 (cb); store 1/(0.9*sum) -----
__global__ void __launch_bounds__(256) maxsum_kernel() {
    int idx = blockIdx.x * blockDim.x + threadIdx.x;  // 0..N*N-1
    const float* p = g_P + idx;
    float mx = __int_as_float(0xff800000);            // -inf
    float s = 0.0f;
    for (int cb = 0; cb < kCB; cb += 8) {
        float v[8];
#pragma unroll
        for (int u = 0; u < 8; u++) v[u] = p[(size_t)(cb + u) * kNN];
#pragma unroll
        for (int u = 0; u < 8; u++) {
            float vv = v[u];
            if (vv > mx) { s = s * __expf(mx - vv) + 1.0f; mx = vv; }
            else         { s += __expf(vv - mx); }
        }
    }
    g_mx[idx] = mx;
    g_sminv[idx] = 1.0f / (kKEEP * s);
}

// ---------------- K4: ctx = dropout(softmax) @ Vh, warp-per-m-column masked skip --
__global__ void __launch_bounds__(256) ctx_kernel(const int* __restrict__ pm,
                                                  float* __restrict__ out) {
    int cb = blockIdx.y;
    int n0 = blockIdx.x * 64;
    int bb = cb & 15;
    const float* Praw = g_P + (size_t)cb * kNN;
    const float* V = g_V + (size_t)cb * kN * kH;

    __shared__ float Pst[64][66];
    __shared__ __align__(16) float Vs[64][32];
    __shared__ int pms[kN];

    int tid = threadIdx.x;                      // 256
    for (int i = tid; i < kN; i += 256) pms[i] = pm[bb * kN + i];

    int w = tid >> 5, l = tid & 31;
    int tx = tid & 7, ty = tid >> 3;
    float acc[2][4] = {};

    __syncthreads();

    for (int m0 = 0; m0 < kN; m0 += 64) {
#pragma unroll
        for (int i = 0; i < 2; i++) {
            int idx = tid + i * 256;
            int k = idx >> 3, h4 = idx & 7;
            *(float4*)&Vs[k][h4 * 4] =
                *(const float4*)&V[(size_t)(m0 + k) * kH + h4 * 4];
        }
#pragma unroll 2
        for (int j = 0; j < 8; j++) {
            int ml = w * 8 + j;
            int m = m0 + ml;
            if (pms[m] == 0 && g_mx[n0 * kN + m] != kNEG) {
                Pst[ml][l] = 0.0f;
                Pst[ml][l + 32] = 0.0f;
            } else {
#pragma unroll
                for (int rr = 0; rr < 2; rr++) {
                    int n = n0 + l + rr * 32;
                    int nm = n * kN + m;
                    uint32_t gi = (uint32_t)(((size_t)cb * kN + n) * kN + m);
                    float v = Praw[(size_t)n * kN + m];
                    float pr = __expf(v - g_mx[nm]) * g_sminv[nm];
                    uint32_t bits = rng_bits(1u, gi);   // key(1)
                    Pst[ml][l + rr * 32] = keep_bit(bits) ? pr : 0.0f;
                }
            }
        }
        __syncthreads();
#pragma unroll
        for (int k = 0; k < 64; k++) {
            float4 v4 = *(const float4*)&Vs[k][tx * 4];
            float2 p2 = *(const float2*)&Pst[k][ty * 2];
            acc[0][0] += p2.x * v4.x; acc[0][1] += p2.x * v4.y;
            acc[0][2] += p2.x * v4.z; acc[0][3] += p2.x * v4.w;
            acc[1][0] += p2.y * v4.x; acc[1][1] += p2.y * v4.y;
            acc[1][2] += p2.y * v4.z; acc[1][3] += p2.y * v4.w;
        }
        __syncthreads();
    }

    int jpart = (cb & 31) * (kN * kB * kH) + (cb >> 5) * kH;
#pragma unroll
    for (int i = 0; i < 2; i++) {
        int n = n0 + ty * 2 + i;
#pragma unroll
        for (int j = 0; j < 4; j++) {
            int h = tx * 4 + j;
            int oidx = jpart + n * (kB * kH) + h;
            uint32_t bits = rng_bits(2u, (uint32_t)oidx);  // key(2)
            out[oidx] = keep_bit(bits) ? acc[i][j] * kRKEEP : 0.0f;
        }
    }
}

// ---------------- K5: attention = dropout(probs)[:, N-1, :] recomputed ------------
__global__ void __launch_bounds__(256) attn_kernel(float* __restrict__ out) {
    int idx = blockIdx.x * blockDim.x + threadIdx.x;  // 0..kATTSZ-1
    int cb = idx >> 9, m = idx & 511;
    uint32_t gi = (uint32_t)(((size_t)cb * kN + (kN - 1)) * kN + m);
    int nm = (kN - 1) * kN + m;
    float v = g_P[gi];
    float pr = __expf(v - g_mx[nm]) * g_sminv[nm];
    uint32_t bits = rng_bits(1u, gi);
    out[kOUTSZ + idx] = keep_bit(bits) ? pr : 0.0f;
}

extern "C" void kernel_launch(void* const* d_in, const int* in_sizes, int n_in,
                              void* d_out, int out_size) {
    const float* x  = (const float*)d_in[0];
    const float* Qp = (const float*)d_in[1];
    const float* Kp = (const float*)d_in[2];
    const float* Vp = (const float*)d_in[3];
    const int*   pm = (const int*)d_in[4];
    float* out = (float*)d_out;

    proj_kernel  <<<dim3(kT / 128, kN / 128, 48), 256>>>(x, Qp, Kp, Vp);
    scores_kernel<<<dim3(kN / 64, kN / 64, kCB), 256>>>(pm);
    maxsum_kernel<<<kNN / 256, 256>>>();
    ctx_kernel   <<<dim3(kN / 64, kCB), 256>>>(pm, out);
    if (out_size >= kOUTSZ + kATTSZ) {
        attn_kernel<<<kATTSZ / 256, 256>>>(out);
    }
}